// round 9
// baseline (speedup 1.0000x reference)
#include <cuda_runtime.h>
#include <cstdint>

#define NSPEC 1024
#define NR1   2048
#define NR2   8192
#define NRTOT (NR1 + NR2)
#define NB    32                   // batches per CTA (lane = batch)
#define WARPS 28
#define THREADS (WARPS * 32)       // 896
#define CHUNKP 8                   // products per chunk
#define NCHUNK (NSPEC / CHUNKP)    // 128
#define YP    33                   // padded row stride (floats)
#define YPB   (YP * 4)             // row stride bytes (132)
#define ONES_ROW NSPEC
#define NSETUP 16                  // CTAs participating in scatter

// ---------------- device scratch ----------------
__device__ int  g_off[NSPEC + 1];
__device__ int  g_cur[NSPEC];      // monotonic across replays (mod-cnt trick)
__device__ int4 g_e[NRTOT];        // .x/.y = byte offs into y_s rows, .z = k bits,
                                   // .w = dst byte off | 1 on last entry of product
__device__ int  g_flag1;           // off[] ready
__device__ int  g_ready;           // scatter done counter (target NSETUP)
__device__ int  g_done;            // CTA completion counter

// ---------------- smem layout (bytes) ----------------
#define SBUF_B   (WARPS * 2 * 32 * 16)             // 28672: double-buffered blocks
#define YS_B     ((NSPEC + 1) * YP * 4)            // 135300
#define TS_B     (NB * 4)                          // 128
#define OTILE_B  (WARPS * CHUNKP * YP * 4)         // 29568
#define SMEM_BYTES (SBUF_B + YS_B + TS_B + OTILE_B)  // 193668

// one entry, fully branchless except a single predicated STS
//   flush flag f = e.w & 1;  mask = f - 1  (f=1 -> 0, f=0 -> 0xFFFFFFFF)
//   acc_next = bits(v) & mask   (kill accumulator on flush, else keep)
#define ENT_BODY(E)                                                             \
    {                                                                           \
        const int4 e = (E);                                                     \
        const float q = *(const float*)(ysl + e.x) * *(const float*)(ysl + e.y);\
        const float v = fmaf(__int_as_float(e.z), q, acc);                      \
        const int   f = e.w & 1;                                                \
        if (f) *(float*)(otl + (e.w & ~3)) = v;                                 \
        acc = __int_as_float(__float_as_int(v) & (f - 1));                      \
    }

extern "C" __global__ void __launch_bounds__(THREADS, 1)
reaction_fused_kernel(const float* __restrict__ t_in,
                      const float* __restrict__ y_in,
                      const float* __restrict__ k1,
                      const float* __restrict__ k2,
                      const int*   __restrict__ i1r,
                      const int*   __restrict__ i1p,
                      const int*   __restrict__ i2r,
                      const int*   __restrict__ i2p,
                      float* __restrict__ y_out,
                      int grid_size) {
    extern __shared__ char smem[];
    int4*  sbuf_all = (int4*)smem;                     // per warp: 2 buffers x 32
    float* y_s      = (float*)(smem + SBUF_B);
    float* t_s      = (float*)(smem + SBUF_B + YS_B);
    char*  otile0   = smem + SBUF_B + YS_B + TS_B;

    const int tid  = threadIdx.x;
    const int lane = tid & 31;
    const int warp = tid >> 5;
    const int cta  = blockIdx.x;
    const int b0   = cta * NB;

    __shared__ int s_chunk;
    if (tid == 0) s_chunk = 0;

    // ============ setup: CTA0 hist+scan; CTAs 0..15 scatter 1/16 each ======
    if (cta == 0) {
        int* s_cnt  = (int*)otile0;            // 1024 ints scratch (pre-hotloop)
        int* s_wsum = s_cnt + NSPEC;           // 16
        for (int i = tid; i < NSPEC; i += THREADS) s_cnt[i] = 0;
        __syncthreads();
        for (int i = tid; i < NR1; i += THREADS) atomicAdd(&s_cnt[i1p[i]], 1);
        for (int i = tid; i < NR2; i += THREADS) atomicAdd(&s_cnt[i2p[i]], 1);
        __syncthreads();
        if (tid < 512) {                       // 16 warps scan 2 bins/thread
            const int a = s_cnt[2 * tid];
            const int b = s_cnt[2 * tid + 1];
            int incl = a + b;
#pragma unroll
            for (int d = 1; d < 32; d <<= 1) {
                int n = __shfl_up_sync(0xFFFFFFFFu, incl, d);
                if (lane >= d) incl += n;
            }
            if (lane == 31) s_wsum[warp] = incl;
            __syncthreads();
            if (warp == 0) {
                int w = (lane < 16) ? s_wsum[lane] : 0;
#pragma unroll
                for (int d = 1; d < 32; d <<= 1) {
                    int n = __shfl_up_sync(0xFFFFFFFFu, w, d);
                    if (lane >= d) w += n;
                }
                if (lane < 16) s_wsum[lane] = w;
            }
            __syncthreads();
            if (warp > 0) incl += s_wsum[warp - 1];
            const int e0 = incl - a - b;
            g_off[2 * tid]     = e0;
            g_off[2 * tid + 1] = e0 + a;
            if (tid == 511) g_off[NSPEC] = incl;
        } else {
            __syncthreads(); __syncthreads();
        }
        __threadfence();
        __syncthreads();
        if (tid == 0) atomicExch(&g_flag1, 1);
    }

    if (cta < NSETUP) {
        if (cta != 0) {
            if (tid == 0) {
                while (atomicAdd(&g_flag1, 0) == 0) __nanosleep(128);
            }
            __syncthreads();
        }
        const int per1 = NR1 / NSETUP, per2 = NR2 / NSETUP;
        for (int r = cta * per1 + tid; r < (cta + 1) * per1; r += THREADS) {
            const int p    = i1p[r];
            const int o0   = g_off[p], o1 = g_off[p + 1];
            const int cnt  = o1 - o0;
            const int posP = atomicAdd(&g_cur[p], 1) % cnt;   // epoch-free
            const int last = (posP == cnt - 1) ? 1 : 0;
            g_e[o0 + posP] = make_int4(i1r[r] * YPB, ONES_ROW * YPB,
                                       __float_as_int(k1[r]),
                                       ((p & (CHUNKP - 1)) * YPB) | last);
        }
        for (int r = cta * per2 + tid; r < (cta + 1) * per2; r += THREADS) {
            const int p    = i2p[r];
            const int o0   = g_off[p], o1 = g_off[p + 1];
            const int cnt  = o1 - o0;
            const int posP = atomicAdd(&g_cur[p], 1) % cnt;
            const int last = (posP == cnt - 1) ? 1 : 0;
            g_e[o0 + posP] = make_int4(i2r[2 * r] * YPB, i2r[2 * r + 1] * YPB,
                                       __float_as_int(k2[r]),
                                       ((p & (CHUNKP - 1)) * YPB) | last);
        }
        __threadfence();
        __syncthreads();
        if (tid == 0) atomicAdd(&g_ready, 1);
    }

    // ============ all CTAs: load y tile transposed into smem ================
    if (tid < NB) t_s[tid] = t_in[b0 + tid];
    if (tid < NB) y_s[ONES_ROW * YP + tid] = 1.0f;
    {
        const float4* y4 = (const float4*)(y_in + (size_t)b0 * NSPEC);
        for (int i = tid; i < NB * NSPEC / 4; i += THREADS) {
            const float4 v = y4[i];
            const int b = i >> 8;
            const int s = (i & 255) * 4;
            y_s[(s + 0) * YP + b] = v.x;
            y_s[(s + 1) * YP + b] = v.y;
            y_s[(s + 2) * YP + b] = v.z;
            y_s[(s + 3) * YP + b] = v.w;
        }
    }

    if (tid == 0) {
        while (atomicAdd(&g_ready, 0) < NSETUP) __nanosleep(128);
    }
    __syncthreads();

    // ============ hot loop: branchless entry body, double-buffered staging ==
    const char* ysl   = (const char*)y_s + lane * 4;   // lane-baked base
    char*       otl   = otile0 + (warp * CHUNKP * YP + lane) * 4;
    int4*       sbufw = sbuf_all + warp * 64;          // 2 buffers x 32

    for (;;) {
        int c;
        if (lane == 0) c = atomicAdd(&s_chunk, 1);
        c = __shfl_sync(0xFFFFFFFFu, c, 0);
        if (c >= NCHUNK) break;
        const int pc = c * CHUNKP;
        const int j0 = g_off[pc];
        const int j1 = g_off[pc + CHUNKP];

#pragma unroll
        for (int pp = 0; pp < CHUNKP; ++pp)
            *(float*)(otl + pp * YPB) = 0.0f;

        float acc = 0.0f;
        int bufsel = 0;

        int4 epf = make_int4(0, 0, 0, 0);
        if (j0 + lane < j1) epf = g_e[j0 + lane];      // coalesced LDG.128

        for (int base = j0; base < j1; base += 32) {
            const int n = min(32, j1 - base);
            int4* sbuf = sbufw + bufsel * 32;
            sbuf[lane] = epf;                           // WAR-safe (double buffer)
            __syncwarp();                               // one barrier per block
            if (base + 32 + lane < j1) epf = g_e[base + 32 + lane];

            if (n == 32) {
#pragma unroll 8
                for (int t = 0; t < 32; ++t) ENT_BODY(sbuf[t])
            } else {
                for (int t = 0; t < n; ++t) ENT_BODY(sbuf[t])
            }
            bufsel ^= 1;
        }
        __syncwarp();   // otile visibility across lanes for transposed read

        // transposed STG.128: lane -> (colgrp = lane&1, row = lane>>1 + 16*it)
        const char* ot_base = otile0 + (warp * CHUNKP * YP) * 4;
        const int   cg4     = (lane & 1) * 4;
#pragma unroll
        for (int it = 0; it < 2; ++it) {
            const int row = (lane >> 1) + 16 * it;
            const float tr = t_s[row];
            float4 v;
            v.x = *(const float*)(ot_base + ((cg4 + 0) * YP + row) * 4) * tr;
            v.y = *(const float*)(ot_base + ((cg4 + 1) * YP + row) * 4) * tr;
            v.z = *(const float*)(ot_base + ((cg4 + 2) * YP + row) * 4) * tr;
            v.w = *(const float*)(ot_base + ((cg4 + 3) * YP + row) * 4) * tr;
            *(float4*)(y_out + (size_t)(b0 + row) * NSPEC + pc + cg4) = v;
        }
        __syncwarp();
    }

    // ============ reset flags for next replay ===============================
    __syncthreads();
    if (tid == 0) {
        const int d = atomicAdd(&g_done, 1);
        if (d == grid_size - 1) {
            atomicExch(&g_ready, 0);
            atomicExch(&g_flag1, 0);
            atomicExch(&g_done, 0);
            // g_cur intentionally NOT reset (mod-cnt epoch trick)
        }
    }
}

// ---------------- launch -----------------------------------------------------
extern "C" void kernel_launch(void* const* d_in, const int* in_sizes, int n_in,
                              void* d_out, int out_size) {
    const float* t_in = (const float*)d_in[0];
    const float* y_in = (const float*)d_in[1];
    const float* k1   = (const float*)d_in[2];
    const float* k2   = (const float*)d_in[3];
    const int*   i1r  = (const int*)d_in[4];
    const int*   i1p  = (const int*)d_in[5];
    const int*   i2r  = (const int*)d_in[6];
    const int*   i2p  = (const int*)d_in[7];
    float* y_out = (float*)d_out;

    const int B    = in_sizes[0];
    const int grid = B / NB;   // 128

    cudaFuncSetAttribute(reaction_fused_kernel,
                         cudaFuncAttributeMaxDynamicSharedMemorySize, SMEM_BYTES);
    reaction_fused_kernel<<<grid, THREADS, SMEM_BYTES>>>(
        t_in, y_in, k1, k2, i1r, i1p, i2r, i2p, y_out, grid);
}

// round 10
// speedup vs baseline: 1.0047x; 1.0047x over previous
#include <cuda_runtime.h>
#include <cstdint>

#define NSPEC 1024
#define NR1   2048
#define NR2   8192
#define NRTOT (NR1 + NR2)
#define NB    32                   // batches per CTA (lane = batch)
#define WARPS 24
#define THREADS (WARPS * 32)       // 768 -> 85 regs/thread available
#define CHUNKP 8                   // products per chunk
#define NCHUNK (NSPEC / CHUNKP)    // 128
#define YP    33                   // padded row stride (floats)
#define YPB   (YP * 4)             // row stride bytes (132)
#define ONES_ROW NSPEC
#define NSETUP 16                  // CTAs participating in scatter
#define GRP   8                    // entries per load-batched group

// ---------------- device scratch ----------------
__device__ int  g_off[NSPEC + 1];
__device__ int  g_cur[NSPEC];      // monotonic across replays (mod-cnt trick)
__device__ int4 g_e[NRTOT];        // .x/.y = byte offs into y_s rows, .z = k bits,
                                   // .w = dst byte off | 1 on last entry of product
__device__ int  g_flag1;           // off[] ready
__device__ int  g_ready;           // scatter done counter (target NSETUP)
__device__ int  g_done;            // CTA completion counter

// ---------------- smem layout (bytes) ----------------
#define SBUF_B   (WARPS * 2 * 32 * 16)             // 24576: double-buffered blocks
#define YS_B     ((NSPEC + 1) * YP * 4)            // 135300
#define TS_B     (NB * 4)                          // 128
#define OTILE_B  (WARPS * CHUNKP * YP * 4)         // 25344
#define SMEM_BYTES (SBUF_B + YS_B + TS_B + OTILE_B)  // 185348

extern "C" __global__ void __launch_bounds__(THREADS, 1)
reaction_fused_kernel(const float* __restrict__ t_in,
                      const float* __restrict__ y_in,
                      const float* __restrict__ k1,
                      const float* __restrict__ k2,
                      const int*   __restrict__ i1r,
                      const int*   __restrict__ i1p,
                      const int*   __restrict__ i2r,
                      const int*   __restrict__ i2p,
                      float* __restrict__ y_out,
                      int grid_size) {
    extern __shared__ char smem[];
    int4*  sbuf_all = (int4*)smem;                     // per warp: 2 buffers x 32
    float* y_s      = (float*)(smem + SBUF_B);
    float* t_s      = (float*)(smem + SBUF_B + YS_B);
    char*  otile0   = smem + SBUF_B + YS_B + TS_B;

    const int tid  = threadIdx.x;
    const int lane = tid & 31;
    const int warp = tid >> 5;
    const int cta  = blockIdx.x;
    const int b0   = cta * NB;

    __shared__ int s_chunk;
    if (tid == 0) s_chunk = 0;

    // ============ setup: CTA0 hist+scan; CTAs 0..15 scatter 1/16 each ======
    if (cta == 0) {
        int* s_cnt  = (int*)otile0;            // 1024 ints scratch (pre-hotloop)
        int* s_wsum = s_cnt + NSPEC;           // 16
        for (int i = tid; i < NSPEC; i += THREADS) s_cnt[i] = 0;
        __syncthreads();
        for (int i = tid; i < NR1; i += THREADS) atomicAdd(&s_cnt[i1p[i]], 1);
        for (int i = tid; i < NR2; i += THREADS) atomicAdd(&s_cnt[i2p[i]], 1);
        __syncthreads();
        if (tid < 512) {                       // 16 warps scan 2 bins/thread
            const int a = s_cnt[2 * tid];
            const int b = s_cnt[2 * tid + 1];
            int incl = a + b;
#pragma unroll
            for (int d = 1; d < 32; d <<= 1) {
                int n = __shfl_up_sync(0xFFFFFFFFu, incl, d);
                if (lane >= d) incl += n;
            }
            if (lane == 31) s_wsum[warp] = incl;
            __syncthreads();
            if (warp == 0) {
                int w = (lane < 16) ? s_wsum[lane] : 0;
#pragma unroll
                for (int d = 1; d < 32; d <<= 1) {
                    int n = __shfl_up_sync(0xFFFFFFFFu, w, d);
                    if (lane >= d) w += n;
                }
                if (lane < 16) s_wsum[lane] = w;
            }
            __syncthreads();
            if (warp > 0) incl += s_wsum[warp - 1];
            const int e0 = incl - a - b;
            g_off[2 * tid]     = e0;
            g_off[2 * tid + 1] = e0 + a;
            if (tid == 511) g_off[NSPEC] = incl;
        } else {
            __syncthreads(); __syncthreads();
        }
        __threadfence();
        __syncthreads();
        if (tid == 0) atomicExch(&g_flag1, 1);
    }

    if (cta < NSETUP) {
        if (cta != 0) {
            if (tid == 0) {
                while (atomicAdd(&g_flag1, 0) == 0) __nanosleep(128);
            }
            __syncthreads();
        }
        const int per1 = NR1 / NSETUP, per2 = NR2 / NSETUP;
        for (int r = cta * per1 + tid; r < (cta + 1) * per1; r += THREADS) {
            const int p    = i1p[r];
            const int o0   = g_off[p], o1 = g_off[p + 1];
            const int cnt  = o1 - o0;
            const int posP = atomicAdd(&g_cur[p], 1) % cnt;   // epoch-free
            const int last = (posP == cnt - 1) ? 1 : 0;
            g_e[o0 + posP] = make_int4(i1r[r] * YPB, ONES_ROW * YPB,
                                       __float_as_int(k1[r]),
                                       ((p & (CHUNKP - 1)) * YPB) | last);
        }
        for (int r = cta * per2 + tid; r < (cta + 1) * per2; r += THREADS) {
            const int p    = i2p[r];
            const int o0   = g_off[p], o1 = g_off[p + 1];
            const int cnt  = o1 - o0;
            const int posP = atomicAdd(&g_cur[p], 1) % cnt;
            const int last = (posP == cnt - 1) ? 1 : 0;
            g_e[o0 + posP] = make_int4(i2r[2 * r] * YPB, i2r[2 * r + 1] * YPB,
                                       __float_as_int(k2[r]),
                                       ((p & (CHUNKP - 1)) * YPB) | last);
        }
        __threadfence();
        __syncthreads();
        if (tid == 0) atomicAdd(&g_ready, 1);
    }

    // ============ all CTAs: load y tile transposed into smem ================
    if (tid < NB) t_s[tid] = t_in[b0 + tid];
    if (tid < NB) y_s[ONES_ROW * YP + tid] = 1.0f;
    {
        const float4* y4 = (const float4*)(y_in + (size_t)b0 * NSPEC);
        for (int i = tid; i < NB * NSPEC / 4; i += THREADS) {
            const float4 v = y4[i];
            const int b = i >> 8;
            const int s = (i & 255) * 4;
            y_s[(s + 0) * YP + b] = v.x;
            y_s[(s + 1) * YP + b] = v.y;
            y_s[(s + 2) * YP + b] = v.z;
            y_s[(s + 3) * YP + b] = v.w;
        }
    }

    if (tid == 0) {
        while (atomicAdd(&g_ready, 0) < NSETUP) __nanosleep(128);
    }
    __syncthreads();

    // ============ hot loop: load-batched groups of 8 entries ================
    const char* ysl   = (const char*)y_s + lane * 4;   // lane-baked base
    char*       otl   = otile0 + (warp * CHUNKP * YP + lane) * 4;
    int4*       sbufw = sbuf_all + warp * 64;          // 2 buffers x 32

    for (;;) {
        int c;
        if (lane == 0) c = atomicAdd(&s_chunk, 1);
        c = __shfl_sync(0xFFFFFFFFu, c, 0);
        if (c >= NCHUNK) break;
        const int pc = c * CHUNKP;
        const int j0 = g_off[pc];
        const int j1 = g_off[pc + CHUNKP];

#pragma unroll
        for (int pp = 0; pp < CHUNKP; ++pp)
            *(float*)(otl + pp * YPB) = 0.0f;

        float acc = 0.0f;
        int bufsel = 0;

        int4 epf = make_int4(0, 0, 0, 0);
        if (j0 + lane < j1) epf = g_e[j0 + lane];      // coalesced LDG.128

        for (int base = j0; base < j1; base += 32) {
            const int n = min(32, j1 - base);
            int4* sbuf = sbufw + bufsel * 32;
            sbuf[lane] = epf;                           // WAR-safe (double buffer)
            __syncwarp();                               // one barrier per block
            if (base + 32 + lane < j1) epf = g_e[base + 32 + lane];

            if (n == 32) {
#pragma unroll
                for (int g = 0; g < 32; g += GRP) {
                    // phase 1: batch-load 8 entry records
                    int4 e[GRP];
#pragma unroll
                    for (int i = 0; i < GRP; ++i) e[i] = sbuf[g + i];
                    // phase 2: batch all 16 gathers (MLP ~16, one 29-cyc wait)
                    float q[GRP];
#pragma unroll
                    for (int i = 0; i < GRP; ++i)
                        q[i] = *(const float*)(ysl + e[i].x) *
                               *(const float*)(ysl + e[i].y);
                    // phase 3: serial FMA/flush chain (overlaps next group's loads)
#pragma unroll
                    for (int i = 0; i < GRP; ++i) {
                        const float v = fmaf(__int_as_float(e[i].z), q[i], acc);
                        const int   f = e[i].w & 1;
                        if (f) *(float*)(otl + (e[i].w & ~3)) = v;
                        acc = __int_as_float(__float_as_int(v) & (f - 1));
                    }
                }
            } else {
                for (int t = 0; t < n; ++t) {
                    const int4 e0 = sbuf[t];
                    const float q0 = *(const float*)(ysl + e0.x) *
                                     *(const float*)(ysl + e0.y);
                    const float v = fmaf(__int_as_float(e0.z), q0, acc);
                    const int   f = e0.w & 1;
                    if (f) *(float*)(otl + (e0.w & ~3)) = v;
                    acc = __int_as_float(__float_as_int(v) & (f - 1));
                }
            }
            bufsel ^= 1;
        }
        __syncwarp();   // otile visibility across lanes for transposed read

        // transposed STG.128: lane -> (colgrp = lane&1, row = lane>>1 + 16*it)
        const char* ot_base = otile0 + (warp * CHUNKP * YP) * 4;
        const int   cg4     = (lane & 1) * 4;
#pragma unroll
        for (int it = 0; it < 2; ++it) {
            const int row = (lane >> 1) + 16 * it;
            const float tr = t_s[row];
            float4 v;
            v.x = *(const float*)(ot_base + ((cg4 + 0) * YP + row) * 4) * tr;
            v.y = *(const float*)(ot_base + ((cg4 + 1) * YP + row) * 4) * tr;
            v.z = *(const float*)(ot_base + ((cg4 + 2) * YP + row) * 4) * tr;
            v.w = *(const float*)(ot_base + ((cg4 + 3) * YP + row) * 4) * tr;
            *(float4*)(y_out + (size_t)(b0 + row) * NSPEC + pc + cg4) = v;
        }
        __syncwarp();
    }

    // ============ reset flags for next replay ===============================
    __syncthreads();
    if (tid == 0) {
        const int d = atomicAdd(&g_done, 1);
        if (d == grid_size - 1) {
            atomicExch(&g_ready, 0);
            atomicExch(&g_flag1, 0);
            atomicExch(&g_done, 0);
            // g_cur intentionally NOT reset (mod-cnt epoch trick)
        }
    }
}

// ---------------- launch -----------------------------------------------------
extern "C" void kernel_launch(void* const* d_in, const int* in_sizes, int n_in,
                              void* d_out, int out_size) {
    const float* t_in = (const float*)d_in[0];
    const float* y_in = (const float*)d_in[1];
    const float* k1   = (const float*)d_in[2];
    const float* k2   = (const float*)d_in[3];
    const int*   i1r  = (const int*)d_in[4];
    const int*   i1p  = (const int*)d_in[5];
    const int*   i2r  = (const int*)d_in[6];
    const int*   i2p  = (const int*)d_in[7];
    float* y_out = (float*)d_out;

    const int B    = in_sizes[0];
    const int grid = B / NB;   // 128

    cudaFuncSetAttribute(reaction_fused_kernel,
                         cudaFuncAttributeMaxDynamicSharedMemorySize, SMEM_BYTES);
    reaction_fused_kernel<<<grid, THREADS, SMEM_BYTES>>>(
        t_in, y_in, k1, k2, i1r, i1p, i2r, i2p, y_out, grid);
}

// round 11
// speedup vs baseline: 1.1001x; 1.0949x over previous
#include <cuda_runtime.h>
#include <cstdint>

#define NSPEC 1024
#define NR1   2048
#define NR2   8192
#define NRTOT (NR1 + NR2)
#define NB    32                   // batches per CTA (lane = batch)
#define WARPS 28
#define THREADS (WARPS * 32)       // 896
#define CHUNKP 8                   // products per chunk
#define NCHUNK (NSPEC / CHUNKP)    // 128
#define YP    33                   // padded row stride (floats)
#define YPB   (YP * 4)             // row stride bytes (132)
#define ONES_ROW NSPEC
#define NSETUP 16                  // CTAs participating in scatter

// ---------------- device scratch ----------------
__device__ int  g_off[NSPEC + 1];
__device__ int  g_cur[NSPEC];      // monotonic across replays (mod-cnt trick)
__device__ int2 g_e[NRTOT];        // .x = ir0*33 | (ir1*33)<<16
                                   // .y = k bits; low 4 bits = (p&7)<<1 | last
__device__ int  g_flag1;           // off[] ready
__device__ int  g_ready;           // scatter done counter (target NSETUP)
__device__ int  g_done;            // CTA completion counter

// ---------------- smem layout (bytes) ----------------
#define SBUF_B   (WARPS * 2 * 32 * 8)              // 14336: double-buffered int2 blocks
#define YS_B     ((NSPEC + 1) * YP * 4)            // 135300
#define TS_B     (NB * 4)                          // 128
#define OTILE_B  (WARPS * CHUNKP * YP * 4)         // 29568
#define SMEM_BYTES (SBUF_B + YS_B + TS_B + OTILE_B)  // 179332

// one PAIR of packed entries (pp = int4 = 2 x int2); 2 crossbar phases/entry
#define PAIR_BODY(PP)                                                           \
    {                                                                           \
        const int4 pp = (PP);                                                   \
        const uint32_t ia = (uint32_t)pp.x;                                     \
        const uint32_t ib = (uint32_t)pp.z;                                     \
        const float qa = *(const float*)(ysl + 4 * (ia & 0xFFFFu)) *            \
                         *(const float*)(ysl + 4 * (ia >> 16));                 \
        const float qb = *(const float*)(ysl + 4 * (ib & 0xFFFFu)) *            \
                         *(const float*)(ysl + 4 * (ib >> 16));                 \
        if (((pp.y | pp.w) & 1) == 0) {                                         \
            /* fast path: no flush in this pair */                              \
            acc = acc + fmaf(__int_as_float(pp.w), qb,                          \
                             __int_as_float(pp.y) * qa);                        \
        } else {                                                                \
            const float v0 = fmaf(__int_as_float(pp.y), qa, acc);               \
            float v1;                                                           \
            if (pp.y & 1) {                                                     \
                *(float*)(otl + (((uint32_t)pp.y >> 1) & 7u) * YPB) = v0;       \
                v1 = __int_as_float(pp.w) * qb;                                 \
            } else {                                                            \
                v1 = fmaf(__int_as_float(pp.w), qb, v0);                        \
            }                                                                   \
            if (pp.w & 1) {                                                     \
                *(float*)(otl + (((uint32_t)pp.w >> 1) & 7u) * YPB) = v1;       \
                acc = 0.0f;                                                     \
            } else {                                                            \
                acc = v1;                                                       \
            }                                                                   \
        }                                                                       \
    }

extern "C" __global__ void __launch_bounds__(THREADS, 1)
reaction_fused_kernel(const float* __restrict__ t_in,
                      const float* __restrict__ y_in,
                      const float* __restrict__ k1,
                      const float* __restrict__ k2,
                      const int*   __restrict__ i1r,
                      const int*   __restrict__ i1p,
                      const int*   __restrict__ i2r,
                      const int*   __restrict__ i2p,
                      float* __restrict__ y_out,
                      int grid_size) {
    extern __shared__ char smem[];
    int2*  sbuf_all = (int2*)smem;                     // per warp: 2 buffers x 32
    float* y_s      = (float*)(smem + SBUF_B);
    float* t_s      = (float*)(smem + SBUF_B + YS_B);
    char*  otile0   = smem + SBUF_B + YS_B + TS_B;

    const int tid  = threadIdx.x;
    const int lane = tid & 31;
    const int warp = tid >> 5;
    const int cta  = blockIdx.x;
    const int b0   = cta * NB;

    __shared__ int s_chunk;
    if (tid == 0) s_chunk = 0;

    // ============ setup: CTA0 hist+scan; CTAs 0..15 scatter 1/16 each ======
    if (cta == 0) {
        int* s_cnt  = (int*)otile0;            // 1024 ints scratch (pre-hotloop)
        int* s_wsum = s_cnt + NSPEC;           // 16
        for (int i = tid; i < NSPEC; i += THREADS) s_cnt[i] = 0;
        __syncthreads();
        for (int i = tid; i < NR1; i += THREADS) atomicAdd(&s_cnt[i1p[i]], 1);
        for (int i = tid; i < NR2; i += THREADS) atomicAdd(&s_cnt[i2p[i]], 1);
        __syncthreads();
        if (tid < 512) {                       // 16 warps scan 2 bins/thread
            const int a = s_cnt[2 * tid];
            const int b = s_cnt[2 * tid + 1];
            int incl = a + b;
#pragma unroll
            for (int d = 1; d < 32; d <<= 1) {
                int n = __shfl_up_sync(0xFFFFFFFFu, incl, d);
                if (lane >= d) incl += n;
            }
            if (lane == 31) s_wsum[warp] = incl;
            __syncthreads();
            if (warp == 0) {
                int w = (lane < 16) ? s_wsum[lane] : 0;
#pragma unroll
                for (int d = 1; d < 32; d <<= 1) {
                    int n = __shfl_up_sync(0xFFFFFFFFu, w, d);
                    if (lane >= d) w += n;
                }
                if (lane < 16) s_wsum[lane] = w;
            }
            __syncthreads();
            if (warp > 0) incl += s_wsum[warp - 1];
            const int e0 = incl - a - b;
            g_off[2 * tid]     = e0;
            g_off[2 * tid + 1] = e0 + a;
            if (tid == 511) g_off[NSPEC] = incl;
        } else {
            __syncthreads(); __syncthreads();
        }
        __threadfence();
        __syncthreads();
        if (tid == 0) atomicExch(&g_flag1, 1);
    }

    if (cta < NSETUP) {
        if (cta != 0) {
            if (tid == 0) {
                while (atomicAdd(&g_flag1, 0) == 0) __nanosleep(128);
            }
            __syncthreads();
        }
        const int per1 = NR1 / NSETUP, per2 = NR2 / NSETUP;
        for (int r = cta * per1 + tid; r < (cta + 1) * per1; r += THREADS) {
            const int p    = i1p[r];
            const int o0   = g_off[p], o1 = g_off[p + 1];
            const int cnt  = o1 - o0;
            const int posP = atomicAdd(&g_cur[p], 1) % cnt;   // epoch-free
            const int last = (posP == cnt - 1) ? 1 : 0;
            g_e[o0 + posP] = make_int2(
                (i1r[r] * 33) | ((ONES_ROW * 33) << 16),
                (__float_as_int(k1[r]) & ~0xF) | ((p & (CHUNKP - 1)) << 1) | last);
        }
        for (int r = cta * per2 + tid; r < (cta + 1) * per2; r += THREADS) {
            const int p    = i2p[r];
            const int o0   = g_off[p], o1 = g_off[p + 1];
            const int cnt  = o1 - o0;
            const int posP = atomicAdd(&g_cur[p], 1) % cnt;
            const int last = (posP == cnt - 1) ? 1 : 0;
            g_e[o0 + posP] = make_int2(
                (i2r[2 * r] * 33) | ((i2r[2 * r + 1] * 33) << 16),
                (__float_as_int(k2[r]) & ~0xF) | ((p & (CHUNKP - 1)) << 1) | last);
        }
        __threadfence();
        __syncthreads();
        if (tid == 0) atomicAdd(&g_ready, 1);
    }

    // ============ all CTAs: load y tile transposed into smem ================
    if (tid < NB) t_s[tid] = t_in[b0 + tid];
    if (tid < NB) y_s[ONES_ROW * YP + tid] = 1.0f;
    {
        const float4* y4 = (const float4*)(y_in + (size_t)b0 * NSPEC);
        for (int i = tid; i < NB * NSPEC / 4; i += THREADS) {
            const float4 v = y4[i];
            const int b = i >> 8;
            const int s = (i & 255) * 4;
            y_s[(s + 0) * YP + b] = v.x;
            y_s[(s + 1) * YP + b] = v.y;
            y_s[(s + 2) * YP + b] = v.z;
            y_s[(s + 3) * YP + b] = v.w;
        }
    }

    if (tid == 0) {
        while (atomicAdd(&g_ready, 0) < NSETUP) __nanosleep(128);
    }
    __syncthreads();

    // ============ hot loop: int2 entries, pair LDS.128, double-buffered =====
    const char* ysl   = (const char*)y_s + lane * 4;   // lane-baked base
    char*       otl   = otile0 + (warp * CHUNKP * YP + lane) * 4;
    int2*       sbufw = sbuf_all + warp * 64;          // 2 buffers x 32 int2

    for (;;) {
        int c;
        if (lane == 0) c = atomicAdd(&s_chunk, 1);
        c = __shfl_sync(0xFFFFFFFFu, c, 0);
        if (c >= NCHUNK) break;
        const int pc = c * CHUNKP;
        const int j0 = g_off[pc];
        const int j1 = g_off[pc + CHUNKP];

#pragma unroll
        for (int pp = 0; pp < CHUNKP; ++pp)
            *(float*)(otl + pp * YPB) = 0.0f;

        float acc = 0.0f;
        int bufsel = 0;

        int2 epf = make_int2(0, 0);
        if (j0 + lane < j1) epf = g_e[j0 + lane];      // coalesced LDG.64

        for (int base = j0; base < j1; base += 32) {
            const int n = min(32, j1 - base);
            int2* buf = sbufw + bufsel * 32;
            buf[lane] = epf;                            // WAR-safe (double buffer)
            __syncwarp();                               // one barrier per block
            if (base + 32 + lane < j1) epf = g_e[base + 32 + lane];

            const int4* sb4 = (const int4*)buf;         // one LDS.128 = one PAIR
            if (n == 32) {
#pragma unroll 8
                for (int t = 0; t < 16; ++t) PAIR_BODY(sb4[t])
            } else {
                const int npairs = n >> 1;
                for (int t = 0; t < npairs; ++t) PAIR_BODY(sb4[t])
                if (n & 1) {                            // odd tail entry
                    const int2 e0 = buf[n - 1];
                    const uint32_t u = (uint32_t)e0.x;
                    const float q = *(const float*)(ysl + 4 * (u & 0xFFFFu)) *
                                    *(const float*)(ysl + 4 * (u >> 16));
                    const float v0 = fmaf(__int_as_float(e0.y), q, acc);
                    if (e0.y & 1) {
                        *(float*)(otl + (((uint32_t)e0.y >> 1) & 7u) * YPB) = v0;
                        acc = 0.0f;
                    } else {
                        acc = v0;
                    }
                }
            }
            bufsel ^= 1;
        }
        __syncwarp();   // otile visibility across lanes for transposed read

        // transposed STG.128: lane -> (colgrp = lane&1, row = lane>>1 + 16*it)
        const char* ot_base = otile0 + (warp * CHUNKP * YP) * 4;
        const int   cg4     = (lane & 1) * 4;
#pragma unroll
        for (int it = 0; it < 2; ++it) {
            const int row = (lane >> 1) + 16 * it;
            const float tr = t_s[row];
            float4 v;
            v.x = *(const float*)(ot_base + ((cg4 + 0) * YP + row) * 4) * tr;
            v.y = *(const float*)(ot_base + ((cg4 + 1) * YP + row) * 4) * tr;
            v.z = *(const float*)(ot_base + ((cg4 + 2) * YP + row) * 4) * tr;
            v.w = *(const float*)(ot_base + ((cg4 + 3) * YP + row) * 4) * tr;
            *(float4*)(y_out + (size_t)(b0 + row) * NSPEC + pc + cg4) = v;
        }
        __syncwarp();
    }

    // ============ reset flags for next replay ===============================
    __syncthreads();
    if (tid == 0) {
        const int d = atomicAdd(&g_done, 1);
        if (d == grid_size - 1) {
            atomicExch(&g_ready, 0);
            atomicExch(&g_flag1, 0);
            atomicExch(&g_done, 0);
            // g_cur intentionally NOT reset (mod-cnt epoch trick)
        }
    }
}

// ---------------- launch -----------------------------------------------------
extern "C" void kernel_launch(void* const* d_in, const int* in_sizes, int n_in,
                              void* d_out, int out_size) {
    const float* t_in = (const float*)d_in[0];
    const float* y_in = (const float*)d_in[1];
    const float* k1   = (const float*)d_in[2];
    const float* k2   = (const float*)d_in[3];
    const int*   i1r  = (const int*)d_in[4];
    const int*   i1p  = (const int*)d_in[5];
    const int*   i2r  = (const int*)d_in[6];
    const int*   i2p  = (const int*)d_in[7];
    float* y_out = (float*)d_out;

    const int B    = in_sizes[0];
    const int grid = B / NB;   // 128

    cudaFuncSetAttribute(reaction_fused_kernel,
                         cudaFuncAttributeMaxDynamicSharedMemorySize, SMEM_BYTES);
    reaction_fused_kernel<<<grid, THREADS, SMEM_BYTES>>>(
        t_in, y_in, k1, k2, i1r, i1p, i2r, i2p, y_out, grid);
}

// round 12
// speedup vs baseline: 1.2056x; 1.0960x over previous
#include <cuda_runtime.h>
#include <cstdint>

#define NSPEC 1024
#define NR1   2048
#define NR2   8192
#define NRTOT (NR1 + NR2)
#define NB    32                   // batches per CTA (lane = batch)
#define WARPS 32
#define THREADS (WARPS * 32)       // 1024
#define CHUNKP 8                   // products per chunk
#define NCHUNK (NSPEC / CHUNKP)    // 128
#define YP    33                   // padded row stride (floats)
#define YPB   (YP * 4)             // row stride bytes (132)
#define ONES_ROW NSPEC
#define NSETUP 16                  // CTAs participating in scatter

// ---------------- device scratch ----------------
__device__ int  g_off[NSPEC + 1];
__device__ int  g_cur[NSPEC];      // monotonic across replays (mod-cnt trick)
__device__ int2 g_e[NRTOT];        // .x = ir0*33 | (ir1*33)<<16
                                   // .y = k bits; low 4 bits = (p&7)<<1 | last
__device__ int  g_flag1;           // off[] ready
__device__ int  g_ready;           // scatter done counter (target NSETUP)
__device__ int  g_done;            // CTA completion counter

// ---------------- smem layout (bytes) ----------------
#define SBUF_B   (WARPS * 2 * 32 * 8)              // 16384: double-buffered int2 blocks
#define YS_B     ((NSPEC + 1) * YP * 4)            // 135300
#define TS_B     (NB * 4)                          // 128
#define OTILE_B  (WARPS * CHUNKP * YP * 4)         // 33792
#define SMEM_BYTES (SBUF_B + YS_B + TS_B + OTILE_B)  // 185604

// one PAIR of packed entries (pp = int4 = 2 x int2)
#define PAIR_BODY(PP)                                                           \
    {                                                                           \
        const int4 pp = (PP);                                                   \
        const uint32_t ia = (uint32_t)pp.x;                                     \
        const uint32_t ib = (uint32_t)pp.z;                                     \
        const float qa = *(const float*)(ysl + 4 * (ia & 0xFFFFu)) *            \
                         *(const float*)(ysl + 4 * (ia >> 16));                 \
        const float qb = *(const float*)(ysl + 4 * (ib & 0xFFFFu)) *            \
                         *(const float*)(ysl + 4 * (ib >> 16));                 \
        if (((pp.y | pp.w) & 1) == 0) {                                         \
            /* fast path: no flush in this pair */                              \
            acc = acc + fmaf(__int_as_float(pp.w), qb,                          \
                             __int_as_float(pp.y) * qa);                        \
        } else {                                                                \
            const float v0 = fmaf(__int_as_float(pp.y), qa, acc);               \
            float v1;                                                           \
            if (pp.y & 1) {                                                     \
                *(float*)(otl + (((uint32_t)pp.y >> 1) & 7u) * YPB) = v0;       \
                v1 = __int_as_float(pp.w) * qb;                                 \
            } else {                                                            \
                v1 = fmaf(__int_as_float(pp.w), qb, v0);                        \
            }                                                                   \
            if (pp.w & 1) {                                                     \
                *(float*)(otl + (((uint32_t)pp.w >> 1) & 7u) * YPB) = v1;       \
                acc = 0.0f;                                                     \
            } else {                                                            \
                acc = v1;                                                       \
            }                                                                   \
        }                                                                       \
    }

extern "C" __global__ void __launch_bounds__(THREADS, 1)
reaction_fused_kernel(const float* __restrict__ t_in,
                      const float* __restrict__ y_in,
                      const float* __restrict__ k1,
                      const float* __restrict__ k2,
                      const int*   __restrict__ i1r,
                      const int*   __restrict__ i1p,
                      const int*   __restrict__ i2r,
                      const int*   __restrict__ i2p,
                      float* __restrict__ y_out,
                      int grid_size) {
    extern __shared__ char smem[];
    int2*  sbuf_all = (int2*)smem;                     // per warp: 2 buffers x 32
    float* y_s      = (float*)(smem + SBUF_B);
    float* t_s      = (float*)(smem + SBUF_B + YS_B);
    char*  otile0   = smem + SBUF_B + YS_B + TS_B;

    const int tid  = threadIdx.x;
    const int lane = tid & 31;
    const int warp = tid >> 5;
    const int cta  = blockIdx.x;
    const int b0   = cta * NB;

    __shared__ int s_chunk;
    if (tid == 0) s_chunk = 0;

    // ============ setup: CTA0 hist+scan; CTAs 0..15 scatter 1/16 each ======
    if (cta == 0) {
        int* s_cnt  = (int*)otile0;            // 1024 ints scratch (pre-hotloop)
        int* s_wsum = s_cnt + NSPEC;           // 16
        for (int i = tid; i < NSPEC; i += THREADS) s_cnt[i] = 0;
        __syncthreads();
        for (int i = tid; i < NR1; i += THREADS) atomicAdd(&s_cnt[i1p[i]], 1);
        for (int i = tid; i < NR2; i += THREADS) atomicAdd(&s_cnt[i2p[i]], 1);
        __syncthreads();
        if (tid < 512) {                       // 16 warps scan 2 bins/thread
            const int a = s_cnt[2 * tid];
            const int b = s_cnt[2 * tid + 1];
            int incl = a + b;
#pragma unroll
            for (int d = 1; d < 32; d <<= 1) {
                int n = __shfl_up_sync(0xFFFFFFFFu, incl, d);
                if (lane >= d) incl += n;
            }
            if (lane == 31) s_wsum[warp] = incl;
            __syncthreads();
            if (warp == 0) {
                int w = (lane < 16) ? s_wsum[lane] : 0;
#pragma unroll
                for (int d = 1; d < 32; d <<= 1) {
                    int n = __shfl_up_sync(0xFFFFFFFFu, w, d);
                    if (lane >= d) w += n;
                }
                if (lane < 16) s_wsum[lane] = w;
            }
            __syncthreads();
            if (warp > 0) incl += s_wsum[warp - 1];
            const int e0 = incl - a - b;
            g_off[2 * tid]     = e0;
            g_off[2 * tid + 1] = e0 + a;
            if (tid == 511) g_off[NSPEC] = incl;
        } else {
            __syncthreads(); __syncthreads();
        }
        __threadfence();
        __syncthreads();
        if (tid == 0) atomicExch(&g_flag1, 1);
    }

    if (cta < NSETUP) {
        if (cta != 0) {
            if (tid == 0) {
                while (atomicAdd(&g_flag1, 0) == 0) __nanosleep(128);
            }
            __syncthreads();
        }
        const int per1 = NR1 / NSETUP, per2 = NR2 / NSETUP;
        for (int r = cta * per1 + tid; r < (cta + 1) * per1; r += THREADS) {
            const int p    = i1p[r];
            const int o0   = g_off[p], o1 = g_off[p + 1];
            const int cnt  = o1 - o0;
            const int posP = atomicAdd(&g_cur[p], 1) % cnt;   // epoch-free
            const int last = (posP == cnt - 1) ? 1 : 0;
            g_e[o0 + posP] = make_int2(
                (i1r[r] * 33) | ((ONES_ROW * 33) << 16),
                (__float_as_int(k1[r]) & ~0xF) | ((p & (CHUNKP - 1)) << 1) | last);
        }
        for (int r = cta * per2 + tid; r < (cta + 1) * per2; r += THREADS) {
            const int p    = i2p[r];
            const int o0   = g_off[p], o1 = g_off[p + 1];
            const int cnt  = o1 - o0;
            const int posP = atomicAdd(&g_cur[p], 1) % cnt;
            const int last = (posP == cnt - 1) ? 1 : 0;
            g_e[o0 + posP] = make_int2(
                (i2r[2 * r] * 33) | ((i2r[2 * r + 1] * 33) << 16),
                (__float_as_int(k2[r]) & ~0xF) | ((p & (CHUNKP - 1)) << 1) | last);
        }
        __threadfence();
        __syncthreads();
        if (tid == 0) atomicAdd(&g_ready, 1);
    }

    // ============ all CTAs: load y tile transposed into smem ================
    // scalar loads: lanes take consecutive species of the SAME batch
    //   -> global: 128B coalesced; smem: addr stride 33 words -> banks l -> conflict-free
    if (tid < NB) t_s[tid] = t_in[b0 + tid];
    if (tid < NB) y_s[ONES_ROW * YP + tid] = 1.0f;
    {
        const float* yb = y_in + (size_t)b0 * NSPEC;
        for (int i = tid; i < NB * NSPEC; i += THREADS) {
            const int b = i >> 10;            // NSPEC == 1024
            const int s = i & (NSPEC - 1);
            y_s[s * YP + b] = yb[(size_t)b * NSPEC + s];
        }
    }

    if (tid == 0) {
        while (atomicAdd(&g_ready, 0) < NSETUP) __nanosleep(128);
    }
    __syncthreads();

    // ============ hot loop: int2 entries, pair LDS.128, double-buffered =====
    const char* ysl   = (const char*)y_s + lane * 4;   // lane-baked base
    char*       otl   = otile0 + (warp * CHUNKP * YP + lane) * 4;
    int2*       sbufw = sbuf_all + warp * 64;          // 2 buffers x 32 int2

    for (;;) {
        int c;
        if (lane == 0) c = atomicAdd(&s_chunk, 1);
        c = __shfl_sync(0xFFFFFFFFu, c, 0);
        if (c >= NCHUNK) break;
        const int pc = c * CHUNKP;
        const int j0 = g_off[pc];
        const int j1 = g_off[pc + CHUNKP];

#pragma unroll
        for (int pp = 0; pp < CHUNKP; ++pp)
            *(float*)(otl + pp * YPB) = 0.0f;

        float acc = 0.0f;
        int bufsel = 0;

        int2 epf = make_int2(0, 0);
        if (j0 + lane < j1) epf = g_e[j0 + lane];      // coalesced LDG.64

        for (int base = j0; base < j1; base += 32) {
            const int n = min(32, j1 - base);
            int2* buf = sbufw + bufsel * 32;
            buf[lane] = epf;                            // WAR-safe (double buffer)
            __syncwarp();                               // one barrier per block
            if (base + 32 + lane < j1) epf = g_e[base + 32 + lane];

            const int4* sb4 = (const int4*)buf;         // one LDS.128 = one PAIR
            if (n == 32) {
#pragma unroll 8
                for (int t = 0; t < 16; ++t) PAIR_BODY(sb4[t])
            } else {
                const int npairs = n >> 1;
                for (int t = 0; t < npairs; ++t) PAIR_BODY(sb4[t])
                if (n & 1) {                            // odd tail entry
                    const int2 e0 = buf[n - 1];
                    const uint32_t u = (uint32_t)e0.x;
                    const float q = *(const float*)(ysl + 4 * (u & 0xFFFFu)) *
                                    *(const float*)(ysl + 4 * (u >> 16));
                    const float v0 = fmaf(__int_as_float(e0.y), q, acc);
                    if (e0.y & 1) {
                        *(float*)(otl + (((uint32_t)e0.y >> 1) & 7u) * YPB) = v0;
                        acc = 0.0f;
                    } else {
                        acc = v0;
                    }
                }
            }
            bufsel ^= 1;
        }
        __syncwarp();   // otile visibility across lanes for transposed read

        // transposed STG.128: lane -> (colgrp = lane&1, row = lane>>1 + 16*it)
        const char* ot_base = otile0 + (warp * CHUNKP * YP) * 4;
        const int   cg4     = (lane & 1) * 4;
#pragma unroll
        for (int it = 0; it < 2; ++it) {
            const int row = (lane >> 1) + 16 * it;
            const float tr = t_s[row];
            float4 v;
            v.x = *(const float*)(ot_base + ((cg4 + 0) * YP + row) * 4) * tr;
            v.y = *(const float*)(ot_base + ((cg4 + 1) * YP + row) * 4) * tr;
            v.z = *(const float*)(ot_base + ((cg4 + 2) * YP + row) * 4) * tr;
            v.w = *(const float*)(ot_base + ((cg4 + 3) * YP + row) * 4) * tr;
            *(float4*)(y_out + (size_t)(b0 + row) * NSPEC + pc + cg4) = v;
        }
        __syncwarp();
    }

    // ============ reset flags for next replay ===============================
    __syncthreads();
    if (tid == 0) {
        const int d = atomicAdd(&g_done, 1);
        if (d == grid_size - 1) {
            atomicExch(&g_ready, 0);
            atomicExch(&g_flag1, 0);
            atomicExch(&g_done, 0);
            // g_cur intentionally NOT reset (mod-cnt epoch trick)
        }
    }
}

// ---------------- launch -----------------------------------------------------
extern "C" void kernel_launch(void* const* d_in, const int* in_sizes, int n_in,
                              void* d_out, int out_size) {
    const float* t_in = (const float*)d_in[0];
    const float* y_in = (const float*)d_in[1];
    const float* k1   = (const float*)d_in[2];
    const float* k2   = (const float*)d_in[3];
    const int*   i1r  = (const int*)d_in[4];
    const int*   i1p  = (const int*)d_in[5];
    const int*   i2r  = (const int*)d_in[6];
    const int*   i2p  = (const int*)d_in[7];
    float* y_out = (float*)d_out;

    const int B    = in_sizes[0];
    const int grid = B / NB;   // 128

    cudaFuncSetAttribute(reaction_fused_kernel,
                         cudaFuncAttributeMaxDynamicSharedMemorySize, SMEM_BYTES);
    reaction_fused_kernel<<<grid, THREADS, SMEM_BYTES>>>(
        t_in, y_in, k1, k2, i1r, i1p, i2r, i2p, y_out, grid);
}

// round 13
// speedup vs baseline: 1.2145x; 1.0073x over previous
#include <cuda_runtime.h>
#include <cstdint>

#define NSPEC 1024
#define NR1   2048
#define NR2   8192
#define NRTOT (NR1 + NR2)
#define NB    32                   // batches per CTA (lane = batch)
#define WARPS 32
#define THREADS (WARPS * 32)       // 1024
#define CHUNKP 8                   // products per chunk
#define NCHUNK (NSPEC / CHUNKP)    // 128
#define YP    33                   // padded row stride (floats)
#define YPB   (YP * 4)             // row stride bytes (132)
#define ONES_ROW NSPEC
#define NSETUP 16                  // CTAs participating in scatter

// ---------------- device scratch ----------------
__device__ int  g_off[NSPEC + 1];
__device__ int  g_cur[NSPEC];      // monotonic across replays (mod-cnt trick)
__device__ int2 g_e[NRTOT];        // .x = ir0*33 | (ir1*33)<<16
                                   // .y = k bits; low 4 bits = (p&7)<<1 | last
__device__ int  g_ready;           // scatter done counter (target NSETUP)
__device__ int  g_done;            // CTA completion counter

// ---------------- smem layout (bytes) ----------------
#define SBUF_B   (WARPS * 2 * 32 * 8)              // 16384: double-buffered int2 blocks
#define YS_B     ((NSPEC + 1) * YP * 4)            // 135300
#define TS_B     (NB * 4)                          // 128
#define OTILE_B  (WARPS * CHUNKP * YP * 4)         // 33792 (also setup scratch)
#define SMEM_BYTES (SBUF_B + YS_B + TS_B + OTILE_B)  // 185604

// one PAIR of packed entries (pp = int4 = 2 x int2)
#define PAIR_BODY(PP)                                                           \
    {                                                                           \
        const int4 pp = (PP);                                                   \
        const uint32_t ia = (uint32_t)pp.x;                                     \
        const uint32_t ib = (uint32_t)pp.z;                                     \
        const float qa = *(const float*)(ysl + 4 * (ia & 0xFFFFu)) *            \
                         *(const float*)(ysl + 4 * (ia >> 16));                 \
        const float qb = *(const float*)(ysl + 4 * (ib & 0xFFFFu)) *            \
                         *(const float*)(ysl + 4 * (ib >> 16));                 \
        if (((pp.y | pp.w) & 1) == 0) {                                         \
            /* fast path: no flush in this pair */                              \
            acc = acc + fmaf(__int_as_float(pp.w), qb,                          \
                             __int_as_float(pp.y) * qa);                        \
        } else {                                                                \
            const float v0 = fmaf(__int_as_float(pp.y), qa, acc);               \
            float v1;                                                           \
            if (pp.y & 1) {                                                     \
                *(float*)(otl + (((uint32_t)pp.y >> 1) & 7u) * YPB) = v0;       \
                v1 = __int_as_float(pp.w) * qb;                                 \
            } else {                                                            \
                v1 = fmaf(__int_as_float(pp.w), qb, v0);                        \
            }                                                                   \
            if (pp.w & 1) {                                                     \
                *(float*)(otl + (((uint32_t)pp.w >> 1) & 7u) * YPB) = v1;       \
                acc = 0.0f;                                                     \
            } else {                                                            \
                acc = v1;                                                       \
            }                                                                   \
        }                                                                       \
    }

extern "C" __global__ void __launch_bounds__(THREADS, 1)
reaction_fused_kernel(const float* __restrict__ t_in,
                      const float* __restrict__ y_in,
                      const float* __restrict__ k1,
                      const float* __restrict__ k2,
                      const int*   __restrict__ i1r,
                      const int*   __restrict__ i1p,
                      const int*   __restrict__ i2r,
                      const int*   __restrict__ i2p,
                      float* __restrict__ y_out,
                      int grid_size) {
    extern __shared__ char smem[];
    int2*  sbuf_all = (int2*)smem;                     // per warp: 2 buffers x 32
    float* y_s      = (float*)(smem + SBUF_B);
    float* t_s      = (float*)(smem + SBUF_B + YS_B);
    char*  otile0   = smem + SBUF_B + YS_B + TS_B;

    const int tid  = threadIdx.x;
    const int lane = tid & 31;
    const int warp = tid >> 5;
    const int cta  = blockIdx.x;
    const int b0   = cta * NB;

    __shared__ int s_chunk;
    if (tid == 0) s_chunk = 0;

    // ============ setup: CTAs 0..15 each build hist+scan LOCALLY, then ======
    // ============ scatter their 1/16 slice (no cross-CTA ordering wait) =====
    if (cta < NSETUP) {
        int* s_cnt  = (int*)otile0;            // 1024 ints (scratch, pre-hotloop)
        int* s_off  = s_cnt + NSPEC;           // 1024 ints (exclusive offsets)
        int* s_wsum = s_off + NSPEC;           // 16

        for (int i = tid; i < NSPEC; i += THREADS) s_cnt[i] = 0;
        __syncthreads();
        for (int i = tid; i < NR1; i += THREADS) atomicAdd(&s_cnt[i1p[i]], 1);
        for (int i = tid; i < NR2; i += THREADS) atomicAdd(&s_cnt[i2p[i]], 1);
        __syncthreads();

        if (tid < 512) {                       // 16 warps scan 2 bins/thread
            const int a = s_cnt[2 * tid];
            const int b = s_cnt[2 * tid + 1];
            int incl = a + b;
#pragma unroll
            for (int d = 1; d < 32; d <<= 1) {
                int n = __shfl_up_sync(0xFFFFFFFFu, incl, d);
                if (lane >= d) incl += n;
            }
            if (lane == 31) s_wsum[warp] = incl;
            __syncthreads();
            if (warp == 0) {
                int w = (lane < 16) ? s_wsum[lane] : 0;
#pragma unroll
                for (int d = 1; d < 32; d <<= 1) {
                    int n = __shfl_up_sync(0xFFFFFFFFu, w, d);
                    if (lane >= d) w += n;
                }
                if (lane < 16) s_wsum[lane] = w;
            }
            __syncthreads();
            if (warp > 0) incl += s_wsum[warp - 1];
            const int e0 = incl - a - b;       // exclusive offset of bin 2*tid
            s_off[2 * tid]     = e0;
            s_off[2 * tid + 1] = e0 + a;
            if (cta == 0) {                    // CTA0 publishes for hot loop
                g_off[2 * tid]     = e0;
                g_off[2 * tid + 1] = e0 + a;
                if (tid == 511) g_off[NSPEC] = incl;
            }
        } else {
            __syncthreads(); __syncthreads();
        }
        __syncthreads();

        // scatter this CTA's 1/16 slice using LOCAL offsets (no global wait)
        const int per1 = NR1 / NSETUP, per2 = NR2 / NSETUP;
        for (int r = cta * per1 + tid; r < (cta + 1) * per1; r += THREADS) {
            const int p    = i1p[r];
            const int o0   = s_off[p];
            const int cnt  = s_cnt[p];
            const int posP = atomicAdd(&g_cur[p], 1) % cnt;   // epoch-free
            const int last = (posP == cnt - 1) ? 1 : 0;
            g_e[o0 + posP] = make_int2(
                (i1r[r] * 33) | ((ONES_ROW * 33) << 16),
                (__float_as_int(k1[r]) & ~0xF) | ((p & (CHUNKP - 1)) << 1) | last);
        }
        for (int r = cta * per2 + tid; r < (cta + 1) * per2; r += THREADS) {
            const int p    = i2p[r];
            const int o0   = s_off[p];
            const int cnt  = s_cnt[p];
            const int posP = atomicAdd(&g_cur[p], 1) % cnt;
            const int last = (posP == cnt - 1) ? 1 : 0;
            g_e[o0 + posP] = make_int2(
                (i2r[2 * r] * 33) | ((i2r[2 * r + 1] * 33) << 16),
                (__float_as_int(k2[r]) & ~0xF) | ((p & (CHUNKP - 1)) << 1) | last);
        }
        __threadfence();
        __syncthreads();
        if (tid == 0) atomicAdd(&g_ready, 1);
    }

    // ============ all CTAs: load y tile transposed into smem ================
    // scalar loads: lanes take consecutive species of the SAME batch
    //   -> global: 128B coalesced; smem: addr stride 33 words -> conflict-free
    if (tid < NB) t_s[tid] = t_in[b0 + tid];
    if (tid < NB) y_s[ONES_ROW * YP + tid] = 1.0f;
    {
        const float* yb = y_in + (size_t)b0 * NSPEC;
        for (int i = tid; i < NB * NSPEC; i += THREADS) {
            const int b = i >> 10;            // NSPEC == 1024
            const int s = i & (NSPEC - 1);
            y_s[s * YP + b] = yb[(size_t)b * NSPEC + s];
        }
    }

    if (tid == 0) {
        while (atomicAdd(&g_ready, 0) < NSETUP) __nanosleep(128);
    }
    __syncthreads();

    // ============ hot loop: int2 entries, pair LDS.128, double-buffered =====
    const char* ysl   = (const char*)y_s + lane * 4;   // lane-baked base
    char*       otl   = otile0 + (warp * CHUNKP * YP + lane) * 4;
    int2*       sbufw = sbuf_all + warp * 64;          // 2 buffers x 32 int2

    for (;;) {
        int c;
        if (lane == 0) c = atomicAdd(&s_chunk, 1);
        c = __shfl_sync(0xFFFFFFFFu, c, 0);
        if (c >= NCHUNK) break;
        const int pc = c * CHUNKP;
        const int j0 = g_off[pc];
        const int j1 = g_off[pc + CHUNKP];

#pragma unroll
        for (int pp = 0; pp < CHUNKP; ++pp)
            *(float*)(otl + pp * YPB) = 0.0f;

        float acc = 0.0f;
        int bufsel = 0;

        int2 epf = make_int2(0, 0);
        if (j0 + lane < j1) epf = g_e[j0 + lane];      // coalesced LDG.64

        for (int base = j0; base < j1; base += 32) {
            const int n = min(32, j1 - base);
            int2* buf = sbufw + bufsel * 32;
            buf[lane] = epf;                            // WAR-safe (double buffer)
            __syncwarp();                               // one barrier per block
            if (base + 32 + lane < j1) epf = g_e[base + 32 + lane];

            const int4* sb4 = (const int4*)buf;         // one LDS.128 = one PAIR
            if (n == 32) {
#pragma unroll 8
                for (int t = 0; t < 16; ++t) PAIR_BODY(sb4[t])
            } else {
                const int npairs = n >> 1;
                for (int t = 0; t < npairs; ++t) PAIR_BODY(sb4[t])
                if (n & 1) {                            // odd tail entry
                    const int2 e0 = buf[n - 1];
                    const uint32_t u = (uint32_t)e0.x;
                    const float q = *(const float*)(ysl + 4 * (u & 0xFFFFu)) *
                                    *(const float*)(ysl + 4 * (u >> 16));
                    const float v0 = fmaf(__int_as_float(e0.y), q, acc);
                    if (e0.y & 1) {
                        *(float*)(otl + (((uint32_t)e0.y >> 1) & 7u) * YPB) = v0;
                        acc = 0.0f;
                    } else {
                        acc = v0;
                    }
                }
            }
            bufsel ^= 1;
        }
        __syncwarp();   // otile visibility across lanes for transposed read

        // transposed STG.128: lane -> (colgrp = lane&1, row = lane>>1 + 16*it)
        const char* ot_base = otile0 + (warp * CHUNKP * YP) * 4;
        const int   cg4     = (lane & 1) * 4;
#pragma unroll
        for (int it = 0; it < 2; ++it) {
            const int row = (lane >> 1) + 16 * it;
            const float tr = t_s[row];
            float4 v;
            v.x = *(const float*)(ot_base + ((cg4 + 0) * YP + row) * 4) * tr;
            v.y = *(const float*)(ot_base + ((cg4 + 1) * YP + row) * 4) * tr;
            v.z = *(const float*)(ot_base + ((cg4 + 2) * YP + row) * 4) * tr;
            v.w = *(const float*)(ot_base + ((cg4 + 3) * YP + row) * 4) * tr;
            *(float4*)(y_out + (size_t)(b0 + row) * NSPEC + pc + cg4) = v;
        }
        __syncwarp();
    }

    // ============ reset flags for next replay ===============================
    __syncthreads();
    if (tid == 0) {
        const int d = atomicAdd(&g_done, 1);
        if (d == grid_size - 1) {
            atomicExch(&g_ready, 0);
            atomicExch(&g_done, 0);
            // g_cur intentionally NOT reset (mod-cnt epoch trick)
        }
    }
}

// ---------------- launch -----------------------------------------------------
extern "C" void kernel_launch(void* const* d_in, const int* in_sizes, int n_in,
                              void* d_out, int out_size) {
    const float* t_in = (const float*)d_in[0];
    const float* y_in = (const float*)d_in[1];
    const float* k1   = (const float*)d_in[2];
    const float* k2   = (const float*)d_in[3];
    const int*   i1r  = (const int*)d_in[4];
    const int*   i1p  = (const int*)d_in[5];
    const int*   i2r  = (const int*)d_in[6];
    const int*   i2p  = (const int*)d_in[7];
    float* y_out = (float*)d_out;

    const int B    = in_sizes[0];
    const int grid = B / NB;   // 128

    cudaFuncSetAttribute(reaction_fused_kernel,
                         cudaFuncAttributeMaxDynamicSharedMemorySize, SMEM_BYTES);
    reaction_fused_kernel<<<grid, THREADS, SMEM_BYTES>>>(
        t_in, y_in, k1, k2, i1r, i1p, i2r, i2p, y_out, grid);
}